// round 16
// baseline (speedup 1.0000x reference)
#include <cuda_runtime.h>

// HH_Synaptic, Round 16: single combined reciprocal for all three gate rails
// (W = rcp(dpqN*dpqM*denH); rr_i = W * product-of-others), pow1/pow2 carried
// as state via pair-powers built in the rcp shadow, output sigmoid from
// eH^4 (no dedicated ex2). MUFUs/step: 9 -> 6. Newton-V and y-series kept.

#define N_DIM 2000
#define L_DIM 1024
#define PF    4

__device__ __forceinline__ float ex2f_(float x){ float r; asm("ex2.approx.f32 %0, %1;" : "=f"(r) : "f"(x)); return r; }
__device__ __forceinline__ float rcpf_(float x){ float r; asm("rcp.approx.f32 %0, %1;" : "=f"(r) : "f"(x)); return r; }

__global__ __launch_bounds__(128, 1)
void hh_synaptic_kernel(const float* __restrict__ z, float* __restrict__ out) {
    const int idx = blockIdx.x * blockDim.x + threadIdx.x;   // 0 .. 16383
    const int b = idx >> 10;
    const int l = idx & (L_DIM - 1);

    const float* zp = z   + (size_t)b * (N_DIM * L_DIM) + l;
    float*       op = out + (size_t)b * (N_DIM * L_DIM) + l;

    const float LOG2E = 1.4426950408889634f;
    const float c9    = LOG2E / 9.0f;
    const float c12   = LOG2E / 12.0f;
    const float cSIG  = LOG2E / 3.0f;
    const float cAH01 = 0.01f * 0.25f * expf(-56.0f / 12.0f);
    const float cOut  = expf(14.0f / 3.0f);      // sigmoid = eH^4/(eH^4 + cOut)

    // Rail constants: N: s=0.02, t=0.002 ; M: s=0.182, t=0.124
    const float sN01 = 2.0e-4f,  tN01 = 2.0e-5f,  RN = 4.0e-4f;
    const float sM01 = 1.82e-3f, tM01 = 1.24e-3f, RM = 3.64e-3f;

    // Singularity-patch constants (reference's exact-equality cases): x' = k*x + c
    const float pN_ = 0.01f*(0.18f+0.08f),  pM_ = 0.01f*(1.638f+1.16f);
    const float kNp = (1.0f-pN_)/(1.0f+pN_), cNp = (0.02f*0.18f)/(1.0f+pN_);
    const float kMp = (1.0f-pM_)/(1.0f+pM_), cMp = (0.02f*1.638f)/(1.0f+pM_);

    // State
    float V = -70.0f;
    float m = 0.0f, n = 0.0f, h = 1.0f, y = 0.0f;
    float pow1 = 0.0f, pow2 = 0.0f;              // 40 m^3 h, 35 n^4 (carried)
    float yG = 1.003f;                           // 1.003 + 0.01*y
    float rP = rcpf_(1.003f);                    // Newton seed (step-1 Gp exact)

    // Pipelined output: row 0 value ready before the loop
    float outPrev;
    {
        float e = ex2f_(-(V + 20.0f) * cSIG);
        outPrev = rcpf_(1.0f + e);
    }
    float* olPrev = op;

    // z prefetch ring: step k consumes z index (k-1)
    float zbuf[PF];
    #pragma unroll
    for (int j = 0; j < PF; ++j)
        zbuf[j] = __ldg(zp + (size_t)j * L_DIM);

    #pragma unroll 4
    for (int k = 1; k < N_DIM; ++k) {
        float zc = zbuf[0];
        #pragma unroll
        for (int j = 0; j < PF - 1; ++j) zbuf[j] = zbuf[j + 1];
        int pidx = min(k - 1 + PF, N_DIM - 1);
        zbuf[PF - 1] = __ldg(zp + (size_t)pidx * L_DIM);

        // ---- head: Gp directly from carried pow1/pow2 ----
        float psum = pow1 + pow2;
        float Gp   = fmaf(0.01f, psum, yG);              // 1 + G

        // ---- spine: r by 2x Newton from previous exact reciprocal ----
        float u1 = fmaf(-Gp, rP, 2.0f);
        float r1 = rP * u1;
        float u2 = fmaf(-Gp, r1, 2.0f);
        float r  = r1 * u2;
        rP = rcpf_(Gp);                                  // off-spine reseed

        // ---- shadow: store previous step's output (pure STG, no MUFU) ----
        *olPrev = outPrev;
        olPrev += L_DIM;

        // ---- shadow: y-rail (series rcp, pY <= 0.011) ----
        float pY = fmaf(0.01f, zc, 0.001f);
        float rY = fmaf(pY, fmaf(pY, 1.0f - pY, -1.0f), 1.0f);
        float yn = fmaf(zc, 0.02f, fmaf(-pY, y, y)) * rY;

        // ---- shadow: patch candidates from old gates ----
        float n_p = fmaf(n, kNp, cNp);
        float m_p = fmaf(m, kMp, cMp);
        float np2 = n_p * n_p;
        float B2p = 35.0f * (np2 * np2);                 // 35 n_p^4
        float mp3 = (m_p * m_p) * m_p;

        // ---- E / num (parallel with Newton) ----
        float E    = fmaf(pow1, 55.0f, fmaf(pow2, -77.0f, -19.5f));
        float b2   = fmaf(0.02f, E, fmaf(2.0f, V, 0.02f));
        float num  = fmaf(-V, Gp, b2);
        float num9  = num * c9;
        float num12 = num * c12;

        // ---- consume r: Vn, dv, ex2 args ----
        float Vn   = num * r;
        float dv25 = fmaf(num,   r, -25.0f);
        float dv35 = fmaf(num,   r,  35.0f);
        float argH = fmaf(num12, r,  34.0f * c12);
        float argN = fmaf(num9,  r, -25.0f * c9);
        float argM = fmaf(num9,  r,  35.0f * c9);

        float eH = ex2f_(argH);
        float eN = ex2f_(argN);
        float eM = ex2f_(argM);

        bool selN = (dv25 == 0.0f);
        bool selM = (dv35 == 0.0f);

        // ---- rail factor prep (ex2 shadow) ----
        float PN  = fmaf( sN01, dv25, 1.0f);
        float QN  = fmaf( tN01, dv25, -1.0f);
        float P2N = fmaf(-sN01, dv25, 1.0f);
        float Q2N = fmaf(-tN01, dv25, -1.0f);
        float RNe = RN * dv25;
        float PM  = fmaf( sM01, dv35, 1.0f);
        float QM  = fmaf( tM01, dv35, -1.0f);
        float P2M = fmaf(-sM01, dv35, 1.0f);
        float Q2M = fmaf(-tM01, dv35, -1.0f);
        float RMe = RM * dv35;

        // ---- H pieces + output (reuses eH^2; no dedicated sigmoid ex2) ----
        float tH2  = eH * eH;
        float denH = fmaf( 0.0025f, tH2, eH + cAH01);
        float wH   = fmaf(-0.0025f, tH2, eH - cAH01);
        float nmH  = fmaf(h, wH, 2.0f * cAH01);
        float T    = tH2 * tH2;                          // eH^4
        float rO   = rcpf_(T + cOut);                    // off-spine
        outPrev    = T * rO;                             // sigmoid((Vn+20)/3)

        // ---- N/M rail pieces; patched dpq := 1 so W stays finite ----
        float dpqN0 = fmaf(eN, PN, QN);
        float dpqM0 = fmaf(eM, PM, QM);
        float dpqN  = selN ? 1.0f : dpqN0;
        float dpqM  = selM ? 1.0f : dpqM0;
        float dmqN  = fmaf(eN, P2N, Q2N);
        float dmqM  = fmaf(eM, P2M, Q2M);
        float nmN   = fmaf(n, dmqN, RNe * eN);
        float nmM   = fmaf(m, dmqM, RMe * eM);

        // ---- ONE combined reciprocal for all rails ----
        float A_NM = dpqN * dpqM;
        float A_NH = dpqN * denH;
        float A_MH = dpqM * denH;
        float Pw   = A_NM * denH;
        float W    = rcpf_(Pw);

        // ---- rcp shadow: pair-power prefactors ----
        float GN  = nmN * A_MH;
        float GN2 = GN * GN;
        float B2  = 35.0f * (GN2 * GN2);                 // 35 (nmN*A_MH)^4
        float GM  = nmM * A_NH;
        float GM3 = (GM * GM) * GM;
        float GH  = nmH * A_NM;
        float B1  = (40.0f * GM3) * GH;
        float C1  = (40.0f * mp3) * GH;                  // m-patch pow1 prefactor

        // ---- consume W ----
        float W2  = W * W;
        float W4  = W2 * W2;
        float rrN = A_MH * W;
        float rrM = A_NH * W;
        float rrH = A_NM * W;
        n = selN ? n_p : nmN * rrN;
        m = selM ? m_p : nmM * rrM;
        h = nmH * rrH;
        pow2 = selN ? B2p      : B2 * W4;                // 35 n'^4
        pow1 = selM ? C1 * W   : B1 * W4;                // 40 m'^3 h'
        y = yn;
        V = Vn;
        yG = fmaf(0.01f, yn, 1.003f);
    }

    // drain the pipelined output (row N_DIM-1)
    *olPrev = outPrev;
}

extern "C" void kernel_launch(void* const* d_in, const int* in_sizes, int n_in,
                              void* d_out, int out_size) {
    const float* z = (const float*)d_in[0];
    float* out = (float*)d_out;
    hh_synaptic_kernel<<<128, 128>>>(z, out);
}

// round 17
// speedup vs baseline: 1.2856x; 1.2856x over previous
#include <cuda_runtime.h>

// HH_Synaptic, Round 17: R15 body with MUFUs cut 9 -> 4.
//  - self-sustaining Newton seed (no reseed rcp)
//  - sigmoid from eH^4 (no dedicated ex2)
//  - ONE rcp serves N-rail, M-rail, H-rail and the sigmoid:
//      W = rcp(dpqN * dpqM * denH * (T + cOut)), rr_i = W * (others)
//    pow1/pow2 still computed from normalized n,m,h at the next head
//    (loop-carried path NOT routed through W — R16's mistake).

#define N_DIM 2000
#define L_DIM 1024
#define PF    4

__device__ __forceinline__ float ex2f_(float x){ float r; asm("ex2.approx.f32 %0, %1;" : "=f"(r) : "f"(x)); return r; }
__device__ __forceinline__ float rcpf_(float x){ float r; asm("rcp.approx.f32 %0, %1;" : "=f"(r) : "f"(x)); return r; }

__global__ __launch_bounds__(128, 1)
void hh_synaptic_kernel(const float* __restrict__ z, float* __restrict__ out) {
    const int idx = blockIdx.x * blockDim.x + threadIdx.x;   // 0 .. 16383
    const int b = idx >> 10;
    const int l = idx & (L_DIM - 1);

    const float* zp = z   + (size_t)b * (N_DIM * L_DIM) + l;
    float*       op = out + (size_t)b * (N_DIM * L_DIM) + l;

    const float LOG2E = 1.4426950408889634f;
    const float c9    = LOG2E / 9.0f;
    const float c12   = LOG2E / 12.0f;
    const float cSIG  = LOG2E / 3.0f;
    const float cAH01 = 0.01f * 0.25f * expf(-56.0f / 12.0f);
    const float cOut  = expf(14.0f / 3.0f);   // sigmoid = eH^4/(eH^4 + cOut)

    // Rail constants: N: s=0.02, t=0.002 ; M: s=0.182, t=0.124
    const float sN01 = 2.0e-4f,  tN01 = 2.0e-5f,  RN = 4.0e-4f;
    const float sM01 = 1.82e-3f, tM01 = 1.24e-3f, RM = 3.64e-3f;

    // Singularity-patch constants (reference's exact-equality cases): x' = k*x + c
    const float pN_ = 0.01f*(0.18f+0.08f),  pM_ = 0.01f*(1.638f+1.16f);
    const float kNp = (1.0f-pN_)/(1.0f+pN_), cNp = (0.02f*0.18f)/(1.0f+pN_);
    const float kMp = (1.0f-pM_)/(1.0f+pM_), cMp = (0.02f*1.638f)/(1.0f+pM_);

    // State
    float V = -70.0f;
    float m = 0.0f, n = 0.0f, h = 1.0f, y = 0.0f;
    float yG = 1.003f;                           // 1.003 + 0.01*y
    float rP = rcpf_(1.003f);                    // Newton seed (step-1 Gp exact)

    // Pipelined output: row 0 value ready before the loop
    float outPrev;
    {
        float e = ex2f_(-(V + 20.0f) * cSIG);
        outPrev = rcpf_(1.0f + e);
    }
    float* olPrev = op;

    // z prefetch ring: step k consumes z index (k-1)
    float zbuf[PF];
    #pragma unroll
    for (int j = 0; j < PF; ++j)
        zbuf[j] = __ldg(zp + (size_t)j * L_DIM);

    #pragma unroll 4
    for (int k = 1; k < N_DIM; ++k) {
        float zc = zbuf[0];
        #pragma unroll
        for (int j = 0; j < PF - 1; ++j) zbuf[j] = zbuf[j + 1];
        int pidx = min(k - 1 + PF, N_DIM - 1);
        zbuf[PF - 1] = __ldg(zp + (size_t)pidx * L_DIM);

        // ---- head: pow chain -> Gp ----
        float mm   = m * m;
        float mh   = m * (40.0f * h);
        float pow1 = mm * mh;                            // GNA*m^3*h
        float n2   = n * n;
        float n35  = 35.0f * n2;
        float pow2 = n2 * n35;                           // GK*n^4
        float psum = pow1 + pow2;
        float Gp   = fmaf(0.01f, psum, yG);              // 1 + G

        // ---- spine: r by 2x Newton, self-sustaining seed (no reseed MUFU) ----
        float u1 = fmaf(-Gp, rP, 2.0f);
        float r1 = rP * u1;
        float u2 = fmaf(-Gp, r1, 2.0f);
        float r  = r1 * u2;
        rP = r;                                          // seed for next step

        // ---- shadow: store previous step's output (pure STG) ----
        *olPrev = outPrev;
        olPrev += L_DIM;

        // ---- shadow: y-rail (series rcp, pY <= 0.011) ----
        float pY = fmaf(0.01f, zc, 0.001f);
        float rY = fmaf(pY, fmaf(pY, 1.0f - pY, -1.0f), 1.0f);
        float yn = fmaf(zc, 0.02f, fmaf(-pY, y, y)) * rY;

        // ---- E / num (parallel with Newton) ----
        float E    = fmaf(pow1, 55.0f, fmaf(pow2, -77.0f, -19.5f));
        float b2   = fmaf(0.02f, E, fmaf(2.0f, V, 0.02f));
        float num  = fmaf(-V, Gp, b2);
        float num9  = num * c9;
        float num12 = num * c12;

        // ---- consume r: Vn, dv, ex2 args ----
        float Vn   = num * r;
        float dv25 = fmaf(num,   r, -25.0f);
        float dv35 = fmaf(num,   r,  35.0f);
        float argN = fmaf(num9,  r, -25.0f * c9);
        float argM = fmaf(num9,  r,  35.0f * c9);
        float argH = fmaf(num12, r,  34.0f * c12);

        float eN = ex2f_(argN);
        float eM = ex2f_(argM);
        float eH = ex2f_(argH);

        bool selN = (dv25 == 0.0f);
        bool selM = (dv35 == 0.0f);

        // ---- rail factor prep (ex2 shadow) ----
        float PN  = fmaf( sN01, dv25, 1.0f);
        float QN  = fmaf( tN01, dv25, -1.0f);
        float P2N = fmaf(-sN01, dv25, 1.0f);
        float Q2N = fmaf(-tN01, dv25, -1.0f);
        float RNe = RN * dv25;
        float PM  = fmaf( sM01, dv35, 1.0f);
        float QM  = fmaf( tM01, dv35, -1.0f);
        float P2M = fmaf(-sM01, dv35, 1.0f);
        float Q2M = fmaf(-tM01, dv35, -1.0f);
        float RMe = RM * dv35;

        // ---- denominators (patched dpq := 1 so W stays finite) ----
        float dpqN0 = fmaf(eN, PN, QN);                  // D + q (N)
        float dpqM0 = fmaf(eM, PM, QM);                  // D + q (M)
        float dpqN  = selN ? 1.0f : dpqN0;
        float dpqM  = selM ? 1.0f : dpqM0;
        float tH2   = eH * eH;
        float denH  = fmaf( 0.0025f, tH2, eH + cAH01);
        float T     = tH2 * tH2;                         // eH^4
        float TpC   = T + cOut;

        // ---- numerators (independent of W) ----
        float dmqN = fmaf(eN, P2N, Q2N);                 // D - q (N)
        float dmqM = fmaf(eM, P2M, Q2M);
        float wH   = fmaf(-0.0025f, tH2, eH - cAH01);
        float nmN  = fmaf(n, dmqN, RNe * eN);
        float nmM  = fmaf(m, dmqM, RMe * eM);
        float nmH  = fmaf(h, wH, 2.0f * cAH01);

        // ---- ONE reciprocal for N, M, H rails AND the sigmoid ----
        float A    = dpqN * dpqM;
        float Pw3  = A * denH;
        float Pw4  = Pw3 * TpC;
        float W    = rcpf_(Pw4);

        // rcp shadow: partial products
        float Bh   = denH * TpC;
        float dMB  = dpqM * Bh;
        float dNB  = dpqN * Bh;
        float ATC  = A * TpC;
        float TP3  = T * Pw3;

        // consume W
        float rrN = dMB * W;     // 1/dpqN
        float rrM = dNB * W;     // 1/dpqM
        float rrH = ATC * W;     // 1/denH
        outPrev   = TP3 * W;     // sigmoid((Vn+20)/3) = T/(T+cOut)

        float resN = nmN * rrN;
        float resM = nmM * rrM;
        float resH = nmH * rrH;

        // reference's exact-equality singularity patches
        n = selN ? fmaf(n, kNp, cNp) : resN;
        m = selM ? fmaf(m, kMp, cMp) : resM;
        h = resH;
        y = yn;
        V = Vn;
        yG = fmaf(0.01f, yn, 1.003f);
    }

    // drain the pipelined output (row N_DIM-1)
    *olPrev = outPrev;
}

extern "C" void kernel_launch(void* const* d_in, const int* in_sizes, int n_in,
                              void* d_out, int out_size) {
    const float* z = (const float*)d_in[0];
    float* out = (float*)d_out;
    hh_synaptic_kernel<<<128, 128>>>(z, out);
}